// round 7
// baseline (speedup 1.0000x reference)
#include <cuda_runtime.h>
#include <cuda_bf16.h>
#include <math.h>

// T=2048 tokens, H=2048 hidden, V=32000 vocab, E=16 experts, top-2.
// Inputs: hidden_states (T*H f32), gate_w (16*H f32), expert_biases (16*V f32).
// Output: bias (T*V f32) then aux_loss (1 f32).

#define NUM_E  16
#define MAX_T  8192
#define NSLICE 4

__device__ float  g_part[NSLICE * MAX_T * NUM_E];  // partial logits per H-slice
__device__ float  g_probs[MAX_T * NUM_E];          // softmax probs per token
__device__ float4 g_meta[MAX_T];                   // (w0, w1, bitcast i0, bitcast i1)

// ---------------------------------------------------------------------------
// Gate phase A: partial logits. Block = 256 thr = 16 tokens x 16 sub-threads.
// Grid = (T/16, NSLICE). Each thread front-batches 8 independent float4 loads
// of its hidden slice (MLP=8 -> hides DRAM latency), then dots against all 16
// experts (gate_w slice is L1-resident). 16-lane butterfly -> one thread
// stores 16 partials as 4x float4.
// ---------------------------------------------------------------------------
__global__ __launch_bounds__(256) void gate_partial_kernel(
    const float* __restrict__ hidden,
    const float* __restrict__ gate_w,
    int H)
{
    const int Hf4  = H >> 2;            // 512
    const int sHf4 = Hf4 / NSLICE;      // 128
    const int tid  = threadIdx.x;
    const int tl   = tid >> 4;          // local token 0..15
    const int sub  = tid & 15;          // sub-thread within token
    const int slice = blockIdx.y;
    const int tok   = blockIdx.x * 16 + tl;

    const float4* __restrict__ hf4 = (const float4*)hidden;
    const float4* __restrict__ gf4 = (const float4*)gate_w;

    const int base = slice * sHf4 + sub;
    const float4* __restrict__ hrow = &hf4[(size_t)tok * Hf4];

    // 8 independent loads up-front
    float4 h[8];
    #pragma unroll
    for (int k = 0; k < 8; k++)
        h[k] = hrow[base + k * 16];

    float acc[NUM_E];
    #pragma unroll
    for (int e = 0; e < NUM_E; e++) acc[e] = 0.0f;

    #pragma unroll
    for (int k = 0; k < 8; k++) {
        const int pos = base + k * 16;
        #pragma unroll
        for (int e = 0; e < NUM_E; e++) {
            float4 g = __ldg(&gf4[(size_t)e * Hf4 + pos]);
            acc[e] += h[k].x*g.x + h[k].y*g.y + h[k].z*g.z + h[k].w*g.w;
        }
    }

    // sum across the 16 sub-threads (lanes within a 16-lane half-warp)
    #pragma unroll
    for (int e = 0; e < NUM_E; e++) {
        float v = acc[e];
        v += __shfl_xor_sync(0xffffffffu, v, 8);
        v += __shfl_xor_sync(0xffffffffu, v, 4);
        v += __shfl_xor_sync(0xffffffffu, v, 2);
        v += __shfl_xor_sync(0xffffffffu, v, 1);
        acc[e] = v;
    }

    if (sub == 0) {
        float4* dst = (float4*)&g_part[((size_t)slice * MAX_T + tok) * NUM_E];
        dst[0] = make_float4(acc[0],  acc[1],  acc[2],  acc[3]);
        dst[1] = make_float4(acc[4],  acc[5],  acc[6],  acc[7]);
        dst[2] = make_float4(acc[8],  acc[9],  acc[10], acc[11]);
        dst[3] = make_float4(acc[12], acc[13], acc[14], acc[15]);
    }
}

// ---------------------------------------------------------------------------
// Gate phase B: combine slice partials, softmax, top-2. One token per thread.
// ---------------------------------------------------------------------------
__global__ __launch_bounds__(256) void gate_finish_kernel(int T)
{
    const int tok = blockIdx.x * 256 + threadIdx.x;
    if (tok >= T) return;

    float l[NUM_E];
    #pragma unroll
    for (int e = 0; e < NUM_E; e++) l[e] = 0.0f;

    #pragma unroll
    for (int s = 0; s < NSLICE; s++) {
        const float4* __restrict__ src =
            (const float4*)&g_part[((size_t)s * MAX_T + tok) * NUM_E];
        #pragma unroll
        for (int c = 0; c < 4; c++) {
            float4 v = src[c];
            l[c*4+0] += v.x; l[c*4+1] += v.y; l[c*4+2] += v.z; l[c*4+3] += v.w;
        }
    }

    float mx = -1e30f;
    #pragma unroll
    for (int e = 0; e < NUM_E; e++) mx = fmaxf(mx, l[e]);
    float p[NUM_E];
    float sum = 0.0f;
    #pragma unroll
    for (int e = 0; e < NUM_E; e++) { p[e] = expf(l[e] - mx); sum += p[e]; }
    float inv = 1.0f / sum;

    int   i0 = 0, i1 = -1;
    float p0 = -1.0f, p1 = -1.0f;
    float4* probs4 = (float4*)&g_probs[(size_t)tok * NUM_E];
    float pr[NUM_E];
    #pragma unroll
    for (int e = 0; e < NUM_E; e++) {
        float pe = p[e] * inv;
        pr[e] = pe;
        if (pe > p0)      { p1 = p0; i1 = i0; p0 = pe; i0 = e; }
        else if (pe > p1) { p1 = pe; i1 = e; }
    }
    #pragma unroll
    for (int c = 0; c < 4; c++)
        probs4[c] = make_float4(pr[c*4], pr[c*4+1], pr[c*4+2], pr[c*4+3]);

    float s2 = p0 + p1;
    float4 m;
    m.x = p0 / s2;
    m.y = p1 / s2;
    m.z = __int_as_float(i0);
    m.w = __int_as_float(i1);
    g_meta[tok] = m;
}

// ---------------------------------------------------------------------------
// Aux loss. Single block, float4 coalesced, deterministic.
// ---------------------------------------------------------------------------
__global__ __launch_bounds__(256) void aux_kernel(float* __restrict__ out_aux, int T)
{
    __shared__ float4 s4[256];
    __shared__ float4 su4[4];
    const int tid = threadIdx.x;
    const int e4  = tid & 3;
    const int c   = tid >> 2;

    const float4* __restrict__ probs4 = (const float4*)g_probs;

    float4 sum = make_float4(0.f, 0.f, 0.f, 0.f);
    for (int t = c; t < T; t += 64) {
        float4 v = probs4[(size_t)t * 4 + e4];
        sum.x += v.x; sum.y += v.y; sum.z += v.z; sum.w += v.w;
    }
    s4[tid] = sum;
    __syncthreads();

    if (tid < 4) {
        float4 u = make_float4(0.f, 0.f, 0.f, 0.f);
        #pragma unroll
        for (int cc = 0; cc < 64; cc++) {
            float4 v = s4[cc * 4 + tid];
            u.x += v.x; u.y += v.y; u.z += v.z; u.w += v.w;
        }
        su4[tid] = u;
    }
    __syncthreads();

    if (tid == 0) {
        float invT = 1.0f / (float)T;
        float aux = 0.0f;
        #pragma unroll
        for (int q = 0; q < 4; q++) {
            float4 u = su4[q];
            float a = u.x * invT, b = u.y * invT, cc = u.z * invT, d = u.w * invT;
            aux += a * logf(a) + b * logf(b) + cc * logf(cc) + d * logf(d);
        }
        out_aux[0] = aux * (float)NUM_E;
    }
}

// ---------------------------------------------------------------------------
// Bias = w0*B[i0] + w1*B[i1]. 262 MB of stores (write-bound, at DRAM floor).
// CHUNK = 512 floats = 2048 B = 16 whole L2 lines -> full-sector writes.
// Streaming stores keep the output out of L2. (R3 config: TOK_GRP=128.)
// ---------------------------------------------------------------------------
#define CHUNK_F4 128          // 512 floats = 2048 B per expert per chunk
#define TOK_GRP  128

__global__ __launch_bounds__(256) void bias_kernel(
    const float* __restrict__ biases,
    float* __restrict__ out,
    int V)
{
    __shared__ float4 sB[NUM_E][CHUNK_F4];   // 32 KB
    __shared__ float4 smeta[TOK_GRP];        // 2 KB

    const int tid   = threadIdx.x;
    const int lane  = tid & 31;
    const int warp  = tid >> 5;
    const int Vf4   = V >> 2;                       // 8000
    const int vbase = blockIdx.x * CHUNK_F4;        // 2048B-aligned
    const int clen  = min(CHUNK_F4, Vf4 - vbase);   // 128 or 64 (tail)
    const int tbase = blockIdx.y * TOK_GRP;

    const float4* __restrict__ bf4 = (const float4*)biases;
    float4* __restrict__ of4 = (float4*)out;

    for (int i = tid; i < NUM_E * CHUNK_F4; i += 256) {
        int e = i >> 7, p = i & (CHUNK_F4 - 1);
        if (p < clen) sB[e][p] = bf4[(size_t)e * Vf4 + vbase + p];
    }
    if (tid < TOK_GRP) smeta[tid] = g_meta[tbase + tid];
    __syncthreads();

    // warp-per-token, lane-contiguous 16B stores (512B/warp bursts)
    for (int t = warp; t < TOK_GRP; t += 8) {
        float4 m = smeta[t];
        const float w0 = m.x, w1 = m.y;
        const int i0 = __float_as_int(m.z);
        const int i1 = __float_as_int(m.w);
        float4* __restrict__ orow = &of4[(size_t)(tbase + t) * Vf4 + vbase];
        #pragma unroll 4
        for (int p = lane; p < clen; p += 32) {
            float4 a = sB[i0][p];
            float4 b = sB[i1][p];
            float4 r;
            r.x = w0 * a.x + w1 * b.x;
            r.y = w0 * a.y + w1 * b.y;
            r.z = w0 * a.z + w1 * b.z;
            r.w = w0 * a.w + w1 * b.w;
            __stcs(&orow[p], r);
        }
    }
}

// ---------------------------------------------------------------------------
extern "C" void kernel_launch(void* const* d_in, const int* in_sizes, int n_in,
                              void* d_out, int out_size)
{
    const float* hidden = (const float*)d_in[0];
    const float* gate_w = (const float*)d_in[1];
    const float* biases = (const float*)d_in[2];
    float* out = (float*)d_out;

    const int H = in_sizes[1] / NUM_E;         // 2048
    const int T = in_sizes[0] / H;             // 2048
    const int V = in_sizes[2] / NUM_E;         // 32000

    // 1a) gate partial logits: (token-group, H-slice) grid
    gate_partial_kernel<<<dim3(T / 16, NSLICE), 256>>>(hidden, gate_w, H);

    // 1b) combine + softmax + top-2
    gate_finish_kernel<<<(T + 255) / 256, 256>>>(T);

    // 2) bias gather+blend
    const int nchunks = (V / 4 + CHUNK_F4 - 1) / CHUNK_F4;   // 63
    dim3 grid(nchunks, T / TOK_GRP);                         // (63, 16)
    bias_kernel<<<grid, 256>>>(biases, out, V);

    // 3) aux loss -> out[T*V]
    aux_kernel<<<1, 256>>>(out + (size_t)T * V, T);
}

// round 9
// speedup vs baseline: 1.1993x; 1.1993x over previous
#include <cuda_runtime.h>
#include <cuda_bf16.h>
#include <math.h>

// T=2048 tokens, H=2048 hidden, V=32000 vocab, E=16 experts, top-2.
// Inputs: hidden_states (T*H f32), gate_w (16*H f32), expert_biases (16*V f32).
// Output: bias (T*V f32) then aux_loss (1 f32).

#define NUM_E 16
#define MAX_T 8192

__device__ float  g_probs[MAX_T * NUM_E];   // softmax probs per token
__device__ float4 g_meta[MAX_T];            // (w0, w1, bitcast i0, bitcast i1)

// ---------------------------------------------------------------------------
// Gate: logits + softmax + top-2, ONE kernel, warp-per-token.
// Block = 256 thr = 8 warps = 8 tokens; grid = T/8 = 256.
// Each lane covers H positions lane + 32*j; h-loads front-batched 8 at a time
// (MLP=8 hides DRAM latency). gate_w (131 KB) is L1-resident. Full-warp
// butterfly -> every lane holds all 16 logits; lane 0 finishes the token.
// ---------------------------------------------------------------------------
__global__ __launch_bounds__(256) void gate_kernel(
    const float* __restrict__ hidden,
    const float* __restrict__ gate_w,
    int H)
{
    const int tid  = threadIdx.x;
    const int lane = tid & 31;
    const int warp = tid >> 5;
    const int Hf4  = H >> 2;            // 512
    const int tok  = blockIdx.x * 8 + warp;

    const float4* __restrict__ hf4 = (const float4*)hidden;
    const float4* __restrict__ gf4 = (const float4*)gate_w;
    const float4* __restrict__ hrow = &hf4[(size_t)tok * Hf4];

    float acc[NUM_E];
    #pragma unroll
    for (int e = 0; e < NUM_E; e++) acc[e] = 0.0f;

    // two halves of H; in each, 8 independent h loads issued up-front
    #pragma unroll
    for (int half = 0; half < 2; half++) {
        const int base = half * (Hf4 >> 1) + lane;   // + j*32, j=0..7

        float4 h[8];
        #pragma unroll
        for (int j = 0; j < 8; j++)
            h[j] = hrow[base + j * 32];

        #pragma unroll
        for (int j = 0; j < 8; j++) {
            const int pos = base + j * 32;
            #pragma unroll
            for (int e = 0; e < NUM_E; e++) {
                float4 g = __ldg(&gf4[(size_t)e * Hf4 + pos]);
                acc[e] += h[j].x*g.x + h[j].y*g.y + h[j].z*g.z + h[j].w*g.w;
            }
        }
    }

    // full-warp butterfly: every lane ends with the complete dot product
    #pragma unroll
    for (int e = 0; e < NUM_E; e++) {
        float v = acc[e];
        v += __shfl_xor_sync(0xffffffffu, v, 16);
        v += __shfl_xor_sync(0xffffffffu, v, 8);
        v += __shfl_xor_sync(0xffffffffu, v, 4);
        v += __shfl_xor_sync(0xffffffffu, v, 2);
        v += __shfl_xor_sync(0xffffffffu, v, 1);
        acc[e] = v;
    }

    if (lane == 0) {
        float mx = -1e30f;
        #pragma unroll
        for (int e = 0; e < NUM_E; e++) mx = fmaxf(mx, acc[e]);
        float p[NUM_E];
        float sum = 0.0f;
        #pragma unroll
        for (int e = 0; e < NUM_E; e++) { p[e] = expf(acc[e] - mx); sum += p[e]; }
        float inv = 1.0f / sum;

        int   i0 = 0, i1 = -1;
        float p0 = -1.0f, p1 = -1.0f;
        float pr[NUM_E];
        #pragma unroll
        for (int e = 0; e < NUM_E; e++) {
            float pe = p[e] * inv;
            pr[e] = pe;
            if (pe > p0)      { p1 = p0; i1 = i0; p0 = pe; i0 = e; }
            else if (pe > p1) { p1 = pe; i1 = e; }
        }
        float4* probs4 = (float4*)&g_probs[(size_t)tok * NUM_E];
        #pragma unroll
        for (int c = 0; c < 4; c++)
            probs4[c] = make_float4(pr[c*4], pr[c*4+1], pr[c*4+2], pr[c*4+3]);

        float s2 = p0 + p1;
        float4 m;
        m.x = p0 / s2;
        m.y = p1 / s2;
        m.z = __int_as_float(i0);
        m.w = __int_as_float(i1);
        g_meta[tok] = m;
    }
}

// ---------------------------------------------------------------------------
// Bias = w0*B[i0] + w1*B[i1] (262 MB stores, write-bound, at DRAM floor:
// 2048B line-aligned chunks + streaming stores). Block (0,0) additionally
// computes the aux loss from g_probs — hidden under the other blocks' work.
// ---------------------------------------------------------------------------
#define CHUNK_F4 128          // 512 floats = 2048 B per expert per chunk
#define TOK_GRP  128

__global__ __launch_bounds__(256) void bias_kernel(
    const float* __restrict__ biases,
    float* __restrict__ out,
    float* __restrict__ out_aux,
    int V, int T)
{
    __shared__ float4 sB[NUM_E][CHUNK_F4];   // 32 KB
    __shared__ float4 smeta[TOK_GRP];        // 2 KB
    __shared__ float4 s4[256];               // 4 KB (aux reduction, block 0,0)
    __shared__ float4 su4[4];

    const int tid   = threadIdx.x;
    const int lane  = tid & 31;
    const int warp  = tid >> 5;
    const int Vf4   = V >> 2;                       // 8000
    const int vbase = blockIdx.x * CHUNK_F4;        // 2048B-aligned
    const int clen  = min(CHUNK_F4, Vf4 - vbase);   // 128 or 64 (tail)
    const int tbase = blockIdx.y * TOK_GRP;

    const float4* __restrict__ bf4 = (const float4*)biases;
    float4* __restrict__ of4 = (float4*)out;

    for (int i = tid; i < NUM_E * CHUNK_F4; i += 256) {
        int e = i >> 7, p = i & (CHUNK_F4 - 1);
        if (p < clen) sB[e][p] = bf4[(size_t)e * Vf4 + vbase + p];
    }
    if (tid < TOK_GRP) smeta[tid] = g_meta[tbase + tid];
    __syncthreads();

    // warp-per-token, lane-contiguous 16B streaming stores
    for (int t = warp; t < TOK_GRP; t += 8) {
        float4 m = smeta[t];
        const float w0 = m.x, w1 = m.y;
        const int i0 = __float_as_int(m.z);
        const int i1 = __float_as_int(m.w);
        float4* __restrict__ orow = &of4[(size_t)(tbase + t) * Vf4 + vbase];
        #pragma unroll 4
        for (int p = lane; p < clen; p += 32) {
            float4 a = sB[i0][p];
            float4 b = sB[i1][p];
            float4 r;
            r.x = w0 * a.x + w1 * b.x;
            r.y = w0 * a.y + w1 * b.y;
            r.z = w0 * a.z + w1 * b.z;
            r.w = w0 * a.w + w1 * b.w;
            __stcs(&orow[p], r);
        }
    }

    // ---- aux loss, computed only by block (0,0), deterministic ----
    if (blockIdx.x == 0 && blockIdx.y == 0) {
        const int e4 = tid & 3;
        const int c  = tid >> 2;
        const float4* __restrict__ probs4 = (const float4*)g_probs;

        float4 sum = make_float4(0.f, 0.f, 0.f, 0.f);
        for (int t = c; t < T; t += 64) {
            float4 v = probs4[(size_t)t * 4 + e4];
            sum.x += v.x; sum.y += v.y; sum.z += v.z; sum.w += v.w;
        }
        s4[tid] = sum;
        __syncthreads();

        if (tid < 4) {
            float4 u = make_float4(0.f, 0.f, 0.f, 0.f);
            #pragma unroll
            for (int cc = 0; cc < 64; cc++) {
                float4 v = s4[cc * 4 + tid];
                u.x += v.x; u.y += v.y; u.z += v.z; u.w += v.w;
            }
            su4[tid] = u;
        }
        __syncthreads();

        if (tid == 0) {
            float invT = 1.0f / (float)T;
            float aux = 0.0f;
            #pragma unroll
            for (int q = 0; q < 4; q++) {
                float4 u = su4[q];
                float a = u.x * invT, b = u.y * invT;
                float cc = u.z * invT, d = u.w * invT;
                aux += a * logf(a) + b * logf(b) + cc * logf(cc) + d * logf(d);
            }
            out_aux[0] = aux * (float)NUM_E;
        }
    }
}

// ---------------------------------------------------------------------------
extern "C" void kernel_launch(void* const* d_in, const int* in_sizes, int n_in,
                              void* d_out, int out_size)
{
    const float* hidden = (const float*)d_in[0];
    const float* gate_w = (const float*)d_in[1];
    const float* biases = (const float*)d_in[2];
    float* out = (float*)d_out;

    const int H = in_sizes[1] / NUM_E;         // 2048
    const int T = in_sizes[0] / H;             // 2048
    const int V = in_sizes[2] / NUM_E;         // 32000

    // 1) gate: one kernel, warp-per-token
    gate_kernel<<<T / 8, 256>>>(hidden, gate_w, H);

    // 2) bias gather+blend (+ aux loss in block (0,0))
    const int nchunks = (V / 4 + CHUNK_F4 - 1) / CHUNK_F4;   // 63
    dim3 grid(nchunks, T / TOK_GRP);                         // (63, 16)
    bias_kernel<<<grid, 256>>>(biases, out, out + (size_t)T * V, V, T);
}